// round 15
// baseline (speedup 1.0000x reference)
#include <cuda_runtime.h>
#include <math.h>

#define NN 50000
#define EE 200000
#define DD 128
#define HH 64
#define TT 4
#define TM 64              // gemm M tile
#define AFS 132            // floats per A-fragment row (128 + pad)
#define GEMM_SMEM (64 * AFS * 4)

// ---------------- scratch (static device globals: allocation-free) ----------
__device__ float    g_xtan[NN * DD];
__device__ float    g_xlin[NN * DD];
__device__ float    g_u[NN * HH];
__device__ float    g_v[NN * HH];
__device__ float    g_wtb[TT * HH];
__device__ float    g_wXf[DD * DD];  // lw^T in mma-B fragment order (tf32)
__device__ float    g_wYf[DD * DD];  // lw^T @ W1ab in fragment order (tf32)
__device__ float    g_bY[DD];        // lb @ W1ab
__device__ int      g_cnt[NN];
__device__ int      g_rowptr[NN + 1];
__device__ int      g_bsum[64];
__device__ int4     g_edata[EE];     // {src, type, w_bits, logw_bits}

// ---------------- helpers ---------------------------------------------------
__device__ __forceinline__ float siluf(float x) {
    return __fdividef(x, 1.0f + __expf(-x));
}
__device__ __forceinline__ unsigned f2tf(float x) {
    unsigned r;
    asm("cvt.rna.tf32.f32 %0, %1;" : "=r"(r) : "f"(x));
    return r;
}
__device__ __forceinline__ void mma8(float* c, const unsigned* a,
                                     unsigned b0, unsigned b1) {
    asm volatile(
        "mma.sync.aligned.m16n8k8.row.col.f32.tf32.tf32.f32 "
        "{%0,%1,%2,%3}, {%4,%5,%6,%7}, {%8,%9}, {%0,%1,%2,%3};"
        : "+f"(c[0]), "+f"(c[1]), "+f"(c[2]), "+f"(c[3])
        : "r"(a[0]), "r"(a[1]), "r"(a[2]), "r"(a[3]), "r"(b0), "r"(b1));
}

// ================== CSR build (graph identical for both layers) ==============
__global__ void k_zero() {
    int i = blockIdx.x * blockDim.x + threadIdx.x;
    if (i < NN) g_cnt[i] = 0;
}
__global__ void k_hist(const int* __restrict__ ei) {
    int e = blockIdx.x * blockDim.x + threadIdx.x;
    if (e < EE) atomicAdd(&g_cnt[__ldg(&ei[EE + e])], 1);
}
__global__ void k_scan1() {
    __shared__ int wsum[32];
    int tid  = threadIdx.x;
    int lane = tid & 31, wid = tid >> 5;
    int i = blockIdx.x * 1024 + tid;
    int v = (i < NN) ? g_cnt[i] : 0;
    int x = v;
#pragma unroll
    for (int o = 1; o < 32; o <<= 1) {
        int y = __shfl_up_sync(0xffffffffu, x, o);
        if (lane >= o) x += y;
    }
    if (lane == 31) wsum[wid] = x;
    __syncthreads();
    if (wid == 0) {
        int y = wsum[lane];
#pragma unroll
        for (int o = 1; o < 32; o <<= 1) {
            int z = __shfl_up_sync(0xffffffffu, y, o);
            if (lane >= o) y += z;
        }
        wsum[lane] = y;
    }
    __syncthreads();
    int wpref = (wid > 0) ? wsum[wid - 1] : 0;
    if (i < NN) g_rowptr[i] = x + wpref - v;
    if (tid == 1023) g_bsum[blockIdx.x] = x + wpref;
}
__global__ void k_scan2(int nblk) {
    __shared__ int w0tot;
    int tid  = threadIdx.x;
    int lane = tid & 31, wid = tid >> 5;
    int v = (tid < nblk) ? g_bsum[tid] : 0;
    int x = v;
#pragma unroll
    for (int o = 1; o < 32; o <<= 1) {
        int y = __shfl_up_sync(0xffffffffu, x, o);
        if (lane >= o) x += y;
    }
    if (tid == 31) w0tot = x;
    __syncthreads();
    if (wid == 1) x += w0tot;
    if (tid < nblk) g_bsum[tid] = x - v;
    if (tid == nblk - 1) g_rowptr[NN] = x;
}
__global__ void k_scan3() {
    int i = blockIdx.x * 1024 + threadIdx.x;
    if (i < NN) { g_rowptr[i] += g_bsum[blockIdx.x]; g_cnt[i] = 0; }
}
__global__ void k_scatter(const int* __restrict__ ei,
                          const int* __restrict__ et,
                          const float* __restrict__ ew) {
    int e = blockIdx.x * blockDim.x + threadIdx.x;
    if (e >= EE) return;
    int dst = __ldg(&ei[EE + e]);
    int pos = g_rowptr[dst] + atomicAdd(&g_cnt[dst], 1);
    float w = __ldg(&ew[e]);
    g_edata[pos] = make_int4(__ldg(&ei[e]), __ldg(&et[e]),
                             __float_as_int(w),
                             __float_as_int(logf(fmaxf(w, 1e-6f))));
}

// ===== weight prep: wXf = lw^T, wYf = lw^T@W1ab, both tf32 + frag order =====
__global__ void k_prep(const float* __restrict__ lw,
                       const float* __restrict__ w1) {
    int idx = blockIdx.x * 256 + threadIdx.x;
    if (idx >= DD * DD) return;
    int k = idx >> 7, c = idx & 127;
    const float* w1c = (c < 64) ? (w1 + c) : (w1 + 128 * 64 + (c - 64));
    float s = 0.f;
#pragma unroll 8
    for (int j = 0; j < 128; j++)
        s = fmaf(__ldg(&lw[j * 128 + k]), __ldg(&w1c[j * 64]), s);
    int koct = k >> 3, klo = k & 7;
    int nb = c >> 3, g = c & 7;
    int off = (koct * 16 + nb) * 64 + (g * 4 + (klo & 3)) * 2 + (klo >> 2);
    g_wYf[off] = __uint_as_float(f2tf(s));
    g_wXf[off] = __uint_as_float(f2tf(__ldg(&lw[c * 128 + k])));
}
// bY[c] = sum_j lb[j] * W1ab[j][c]  (warp per output, lane-parallel)
__global__ void k_prepb(const float* __restrict__ lb,
                        const float* __restrict__ w1) {
    int c    = blockIdx.x * 8 + (threadIdx.x >> 5);
    int lane = threadIdx.x & 31;
    if (c >= DD) return;
    const float* w1c = (c < 64) ? (w1 + c) : (w1 + 128 * 64 + (c - 64));
    float b = 0.f;
#pragma unroll
    for (int i = 0; i < 4; i++) {
        int j = lane + 32 * i;
        b = fmaf(__ldg(&lb[j]), __ldg(&w1c[j * 64]), b);
    }
#pragma unroll
    for (int o = 16; o; o >>= 1) b += __shfl_xor_sync(0xffffffffu, b, o);
    if (lane == 0) g_bY[c] = b;
}

// -------- unified tf32 GEMM: merged phases — one A load, both weights --------
// prologue: log-map xh(N,129) -> AF (mma-fragment layout, tf32) + g_xtan
// single mainloop: accX += A*wX, accY += A*wY (16 indep MMAs per k-octet)
__global__ __launch_bounds__(256, 2) void k_gemm2(
    const float* __restrict__ xh, const float* __restrict__ curv,
    const float* __restrict__ lb) {
    extern __shared__ float sm[];
    float* AF = sm;             // [4 m16][16 ksg][AFS]
    int tid  = threadIdx.x;
    int lane = tid & 31;
    int w    = tid >> 5;
    int g    = lane >> 2;
    int t    = lane & 3;
    int mw   = w & 1;
    int nw   = w >> 1;
    int n0   = blockIdx.x * TM;

    // prologue: log-map 8 rows per warp (pairs for ILP), scatter to AF
    {
        float c   = fminf(fmaxf(__ldg(&curv[0]), 0.1f), 10.0f);
        float sqc = sqrtf(c);
        int rbase = w * 8;
        int ksg_w = lane >> 1;
        int khi_w = lane & 1;
#pragma unroll
        for (int rr = 0; rr < 8; rr += 2) {
            int mA = rbase + rr, mB = mA + 1;
            int nA = n0 + mA, nB = n0 + mB;
            float spA[4] = {0.f, 0.f, 0.f, 0.f};
            float spB[4] = {0.f, 0.f, 0.f, 0.f};
            float x0A = 1.f, x0B = 1.f, nsA = 0.f, nsB = 0.f;
            if (nA < NN) {
                const float* row = xh + (size_t)nA * 129;
                x0A = __ldg(&row[0]);
#pragma unroll
                for (int i = 0; i < 4; i++) {
                    spA[i] = __ldg(&row[1 + 4 * lane + i]);
                    nsA += spA[i] * spA[i];
                }
            }
            if (nB < NN) {
                const float* row = xh + (size_t)nB * 129;
                x0B = __ldg(&row[0]);
#pragma unroll
                for (int i = 0; i < 4; i++) {
                    spB[i] = __ldg(&row[1 + 4 * lane + i]);
                    nsB += spB[i] * spB[i];
                }
            }
#pragma unroll
            for (int o = 16; o; o >>= 1) {
                nsA += __shfl_xor_sync(0xffffffffu, nsA, o);
                nsB += __shfl_xor_sync(0xffffffffu, nsB, o);
            }
            float nrmA = fmaxf(sqrtf(nsA), 1e-6f);
            float nrmB = fmaxf(sqrtf(nsB), 1e-6f);
            float scA = (nA < NN)
                ? acoshf(fmaxf(sqc * x0A, 1.0f + 1e-7f)) / (sqc * nrmA) : 0.f;
            float scB = (nB < NN)
                ? acoshf(fmaxf(sqc * x0B, 1.0f + 1e-7f)) / (sqc * nrmB) : 0.f;
            float4 xvA = make_float4(spA[0] * scA, spA[1] * scA,
                                     spA[2] * scA, spA[3] * scA);
            float4 xvB = make_float4(spB[0] * scB, spB[1] * scB,
                                     spB[2] * scB, spB[3] * scB);
            if (nA < NN) *(float4*)&g_xtan[(size_t)nA * DD + 4 * lane] = xvA;
            if (nB < NN) *(float4*)&g_xtan[(size_t)nB * DD + 4 * lane] = xvB;
            {
                int m16 = mA >> 4, gr = mA & 7, hi = (mA >> 3) & 1;
                float* base = &AF[(m16 * 16 + ksg_w) * AFS + hi + 2 * khi_w];
                base[(gr * 4 + 0) * 4] = __uint_as_float(f2tf(xvA.x));
                base[(gr * 4 + 1) * 4] = __uint_as_float(f2tf(xvA.y));
                base[(gr * 4 + 2) * 4] = __uint_as_float(f2tf(xvA.z));
                base[(gr * 4 + 3) * 4] = __uint_as_float(f2tf(xvA.w));
            }
            {
                int m16 = mB >> 4, gr = mB & 7, hi = (mB >> 3) & 1;
                float* base = &AF[(m16 * 16 + ksg_w) * AFS + hi + 2 * khi_w];
                base[(gr * 4 + 0) * 4] = __uint_as_float(f2tf(xvB.x));
                base[(gr * 4 + 1) * 4] = __uint_as_float(f2tf(xvB.y));
                base[(gr * 4 + 2) * 4] = __uint_as_float(f2tf(xvB.z));
                base[(gr * 4 + 3) * 4] = __uint_as_float(f2tf(xvB.w));
            }
        }
    }
    __syncthreads();  // AF complete; no further barriers

    float accX[2][4][4], accY[2][4][4];
#pragma unroll
    for (int mi = 0; mi < 2; mi++)
#pragma unroll
        for (int nj = 0; nj < 4; nj++)
#pragma unroll
            for (int q = 0; q < 4; q++) {
                accX[mi][nj][q] = 0.f;
                accY[mi][nj][q] = 0.f;
            }

#pragma unroll 2
    for (int ksg = 0; ksg < 16; ksg++) {
        float2 bX[4], bY[4];
#pragma unroll
        for (int nj = 0; nj < 4; nj++) {
            int off = (ksg * 16 + nw * 4 + nj) * 64 + lane * 2;
            bX[nj] = *(const float2*)&g_wXf[off];
            bY[nj] = *(const float2*)&g_wYf[off];
        }
        unsigned a[2][4];
#pragma unroll
        for (int mi = 0; mi < 2; mi++) {
            float4 af = *(const float4*)
                &AF[((mw * 2 + mi) * 16 + ksg) * AFS + lane * 4];
            a[mi][0] = __float_as_uint(af.x);
            a[mi][1] = __float_as_uint(af.y);
            a[mi][2] = __float_as_uint(af.z);
            a[mi][3] = __float_as_uint(af.w);
        }
#pragma unroll
        for (int nj = 0; nj < 4; nj++) {
            mma8(accX[0][nj], a[0], __float_as_uint(bX[nj].x),
                 __float_as_uint(bX[nj].y));
            mma8(accX[1][nj], a[1], __float_as_uint(bX[nj].x),
                 __float_as_uint(bX[nj].y));
            mma8(accY[0][nj], a[0], __float_as_uint(bY[nj].x),
                 __float_as_uint(bY[nj].y));
            mma8(accY[1][nj], a[1], __float_as_uint(bY[nj].x),
                 __float_as_uint(bY[nj].y));
        }
    }

    // epilogue: phase-X -> g_xlin (+lb), phase-Y -> u/v (+bY)
#pragma unroll
    for (int mi = 0; mi < 2; mi++)
#pragma unroll
        for (int nj = 0; nj < 4; nj++) {
            int cb = nw * 32 + nj * 8 + 2 * t;
            int rl0 = mw * 32 + mi * 16 + g, rl1 = rl0 + 8;
            int gn0 = n0 + rl0, gn1 = n0 + rl1;
            float lb0 = __ldg(&lb[cb]), lb1 = __ldg(&lb[cb + 1]);
            float by0 = g_bY[cb],       by1 = g_bY[cb + 1];
            float2 sx0 = make_float2(accX[mi][nj][0] + lb0,
                                     accX[mi][nj][1] + lb1);
            float2 sx1 = make_float2(accX[mi][nj][2] + lb0,
                                     accX[mi][nj][3] + lb1);
            float2 sy0 = make_float2(accY[mi][nj][0] + by0,
                                     accY[mi][nj][1] + by1);
            float2 sy1 = make_float2(accY[mi][nj][2] + by0,
                                     accY[mi][nj][3] + by1);
            if (gn0 < NN) *(float2*)&g_xlin[(size_t)gn0 * DD + cb] = sx0;
            if (gn1 < NN) *(float2*)&g_xlin[(size_t)gn1 * DD + cb] = sx1;
            if (cb < 64) {
                if (gn0 < NN) *(float2*)&g_u[(size_t)gn0 * HH + cb] = sy0;
                if (gn1 < NN) *(float2*)&g_u[(size_t)gn1 * HH + cb] = sy1;
            } else {
                if (gn0 < NN) *(float2*)&g_v[(size_t)gn0 * HH + cb - 64] = sy0;
                if (gn1 < NN) *(float2*)&g_v[(size_t)gn1 * HH + cb - 64] = sy1;
            }
        }
}

// ---------------- wtb[t][h] = emb[t] . W1c[:,h] + b1[h] ----------------------
__global__ void k_wtb(const float* __restrict__ emb,
                      const float* __restrict__ w1,
                      const float* __restrict__ b1) {
    int w    = blockIdx.x * 8 + (threadIdx.x >> 5);
    int lane = threadIdx.x & 31;
    if (w >= TT * HH) return;
    int t = w >> 6, h = w & 63;
    float s = 0.f;
#pragma unroll
    for (int i = 0; i < 4; i++) {
        int k = lane + 32 * i;
        s = fmaf(__ldg(&emb[t * DD + k]), __ldg(&w1[(2 * DD + k) * HH + h]), s);
    }
#pragma unroll
    for (int o = 16; o; o >>= 1) s += __shfl_xor_sync(0xffffffffu, s, o);
    if (lane == 0) g_wtb[w] = s + __ldg(&b1[h]);
}

// ====== fused per-dst: no-max softmax (scores tiny) + agg + LN + exp map =====
__global__ __launch_bounds__(256) void k_fused(
    const float* __restrict__ emb,
    const float* __restrict__ aw2, const float* __restrict__ ab2,
    const float* __restrict__ sib, const float* __restrict__ lng,
    const float* __restrict__ lnb, const float* __restrict__ curv,
    float* __restrict__ out) {
    __shared__ float swtb[TT * HH];
    __shared__ float sw2[HH];
    __shared__ float semb[TT * DD];
    int tid = threadIdx.x;
    if (tid < TT * HH) swtb[tid] = g_wtb[tid];
    if (tid < HH) sw2[tid] = __ldg(&aw2[tid]);
    for (int i = tid; i < TT * DD; i += 256) semb[i] = __ldg(&emb[i]);
    __syncthreads();

    int n    = blockIdx.x * 8 + (tid >> 5);
    int lane = tid & 31;
    if (n >= NN) return;
    float b2 = __ldg(&ab2[0]);
    float sb = __ldg(&sib[0]);
    float2 uu = *(const float2*)&g_u[(size_t)n * HH + 2 * lane];
    float w2a = sw2[2 * lane], w2b = sw2[2 * lane + 1];

    int p0 = g_rowptr[n], p1 = g_rowptr[n + 1];
    float s = 0.f;
    float a0 = 0.f, a1 = 0.f, a2 = 0.f, a3 = 0.f;
    int p = p0;
    for (; p + 2 <= p1; p += 2) {
        int4 e0 = __ldg(&g_edata[p]);
        int4 e1 = __ldg(&g_edata[p + 1]);
        float2 v0 = *(const float2*)&g_v[(size_t)e0.x * HH + 2 * lane];
        float2 v1 = *(const float2*)&g_v[(size_t)e1.x * HH + 2 * lane];
        float4 x0 = *(const float4*)&g_xlin[(size_t)e0.x * DD + 4 * lane];
        float4 x1 = *(const float4*)&g_xlin[(size_t)e1.x * DD + 4 * lane];
        float z0a = uu.x + v0.x + swtb[e0.y * HH + 2 * lane];
        float z0b = uu.y + v0.y + swtb[e0.y * HH + 2 * lane + 1];
        float z1a = uu.x + v1.x + swtb[e1.y * HH + 2 * lane];
        float z1b = uu.y + v1.y + swtb[e1.y * HH + 2 * lane + 1];
        float pp0 = siluf(z0a) * w2a + siluf(z0b) * w2b;
        float pp1 = siluf(z1a) * w2a + siluf(z1b) * w2b;
#pragma unroll
        for (int o = 16; o; o >>= 1) {
            pp0 += __shfl_xor_sync(0xffffffffu, pp0, o);
            pp1 += __shfl_xor_sync(0xffffffffu, pp1, o);
        }
        float s0 = pp0 + b2 + __int_as_float(e0.w);
        float s1 = pp1 + b2 + __int_as_float(e1.w);
        if (e0.y == 1) s0 += sb;
        if (e1.y == 1) s1 += sb;
        float ex0 = __expf(s0);
        float ex1 = __expf(s1);
        s += ex0 + ex1;
        float cw0 = ex0 * __int_as_float(e0.z);
        float cw1 = ex1 * __int_as_float(e1.z);
        const float4 m0 = *(const float4*)&semb[e0.y * DD + 4 * lane];
        const float4 m1 = *(const float4*)&semb[e1.y * DD + 4 * lane];
        a0 += cw0 * (x0.x + m0.x) + cw1 * (x1.x + m1.x);
        a1 += cw0 * (x0.y + m0.y) + cw1 * (x1.y + m1.y);
        a2 += cw0 * (x0.z + m0.z) + cw1 * (x1.z + m1.z);
        a3 += cw0 * (x0.w + m0.w) + cw1 * (x1.w + m1.w);
    }
    if (p < p1) {
        int4 e0 = __ldg(&g_edata[p]);
        float2 v0 = *(const float2*)&g_v[(size_t)e0.x * HH + 2 * lane];
        float4 x0 = *(const float4*)&g_xlin[(size_t)e0.x * DD + 4 * lane];
        float z0a = uu.x + v0.x + swtb[e0.y * HH + 2 * lane];
        float z0b = uu.y + v0.y + swtb[e0.y * HH + 2 * lane + 1];
        float pp0 = siluf(z0a) * w2a + siluf(z0b) * w2b;
#pragma unroll
        for (int o = 16; o; o >>= 1)
            pp0 += __shfl_xor_sync(0xffffffffu, pp0, o);
        float s0 = pp0 + b2 + __int_as_float(e0.w);
        if (e0.y == 1) s0 += sb;
        float ex0 = __expf(s0);
        s += ex0;
        float cw0 = ex0 * __int_as_float(e0.z);
        const float4 m0 = *(const float4*)&semb[e0.y * DD + 4 * lane];
        a0 += cw0 * (x0.x + m0.x);
        a1 += cw0 * (x0.y + m0.y);
        a2 += cw0 * (x0.z + m0.z);
        a3 += cw0 * (x0.w + m0.w);
    }
    float inv = __fdividef(1.f, s + 1e-16f);

    float4 xt = *(const float4*)&g_xtan[(size_t)n * DD + 4 * lane];
    float x[4];
    x[0] = xt.x + a0 * inv; x[1] = xt.y + a1 * inv;
    x[2] = xt.z + a2 * inv; x[3] = xt.w + a3 * inv;
    float sm = x[0] + x[1] + x[2] + x[3];
#pragma unroll
    for (int o = 16; o; o >>= 1) sm += __shfl_xor_sync(0xffffffffu, sm, o);
    float mu = sm * (1.0f / 128.0f);
    float vs = 0.f;
#pragma unroll
    for (int i = 0; i < 4; i++) { float d = x[i] - mu; vs += d * d; }
#pragma unroll
    for (int o = 16; o; o >>= 1) vs += __shfl_xor_sync(0xffffffffu, vs, o);
    float rinv = rsqrtf(vs * (1.0f / 128.0f) + 1e-5f);
    float y[4];
    float n2 = 0.f;
#pragma unroll
    for (int i = 0; i < 4; i++) {
        y[i] = (x[i] - mu) * rinv * __ldg(&lng[4 * lane + i]) +
               __ldg(&lnb[4 * lane + i]);
        n2 += y[i] * y[i];
    }
#pragma unroll
    for (int o = 16; o; o >>= 1) n2 += __shfl_xor_sync(0xffffffffu, n2, o);
    float c   = fminf(fmaxf(__ldg(&curv[0]), 0.1f), 10.0f);
    float sqc = sqrtf(c);
    float nrm = fmaxf(sqrtf(n2), 1e-6f);
    float th  = sqc * nrm;
    float scale = sinhf(th) / (sqc * nrm);
    float* orow = out + (size_t)n * 129;
    if (lane == 0) orow[0] = coshf(th) / sqc;
#pragma unroll
    for (int i = 0; i < 4; i++) orow[1 + 4 * lane + i] = y[i] * scale;
}

// ---------------- host ------------------------------------------------------
extern "C" void kernel_launch(void* const* d_in, const int* in_sizes, int n_in,
                              void* d_out, int out_size) {
    const float* x_hyp = (const float*)d_in[0];
    const int*   ei    = (const int*)d_in[1];
    const int*   et    = (const int*)d_in[2];
    const float* ew    = (const float*)d_in[3];
    const float* lin_w = (const float*)d_in[4];
    const float* lin_b = (const float*)d_in[5];
    const float* ln_g  = (const float*)d_in[6];
    const float* ln_b  = (const float*)d_in[7];
    const float* eemb  = (const float*)d_in[8];
    const float* aw1   = (const float*)d_in[9];
    const float* ab1   = (const float*)d_in[10];
    const float* aw2   = (const float*)d_in[11];
    const float* ab2   = (const float*)d_in[12];
    const float* sib   = (const float*)d_in[13];
    const float* curv  = (const float*)d_in[14];
    float* out = (float*)d_out;
    (void)in_sizes; (void)n_in; (void)out_size;

    cudaFuncSetAttribute(k_gemm2, cudaFuncAttributeMaxDynamicSharedMemorySize,
                         GEMM_SMEM);

    const int NSCAN = (NN + 1023) / 1024;  // 49
    // layer 0 (k_gemm2 L0 at launch index 3 — ncu profiles index 3)
    k_zero<<<(NN + 255) / 256, 256>>>();
    k_prep<<<64, 256>>>(lin_w, aw1);
    k_prepb<<<16, 256>>>(lin_b, aw1);
    k_gemm2<<<(NN + TM - 1) / TM, 256, GEMM_SMEM>>>(x_hyp, curv + 0, lin_b);
    k_hist<<<(EE + 255) / 256, 256>>>(ei);
    k_scan1<<<NSCAN, 1024>>>();
    k_scan2<<<1, 64>>>(NSCAN);
    k_scan3<<<NSCAN, 1024>>>();
    k_scatter<<<(EE + 255) / 256, 256>>>(ei, et, ew);
    k_wtb<<<32, 256>>>(eemb, aw1, ab1);
    k_fused<<<(NN + 7) / 8, 256>>>(eemb, aw2, ab2, sib, ln_g, ln_b, curv, out);

    // layer 1
    k_prep<<<64, 256>>>(lin_w + DD * DD, aw1 + 3 * DD * HH);
    k_prepb<<<16, 256>>>(lin_b + DD, aw1 + 3 * DD * HH);
    k_gemm2<<<(NN + TM - 1) / TM, 256, GEMM_SMEM>>>(out, curv + 1,
                                                    lin_b + DD);
    k_wtb<<<32, 256>>>(eemb + TT * DD, aw1 + 3 * DD * HH, ab1 + HH);
    k_fused<<<(NN + 7) / 8, 256>>>(eemb + TT * DD, aw2 + HH, ab2 + 1, sib + 1,
                                   ln_g + DD, ln_b + DD, curv + 1, out);
}

// round 17
// speedup vs baseline: 1.0416x; 1.0416x over previous
#include <cuda_runtime.h>
#include <math.h>

#define NN 50000
#define EE 200000
#define DD 128
#define HH 64
#define TT 4
#define TM 64              // gemm M tile
#define AFS 132            // floats per A-fragment row (128 + pad)
#define GEMM_SMEM (64 * AFS * 4)

// ---------------- scratch (static device globals: allocation-free) ----------
__device__ float    g_xtan[NN * DD];
__device__ float    g_xlin[NN * DD];
__device__ float    g_u[NN * HH];
__device__ float    g_v[NN * HH];
__device__ float    g_wtb[2 * TT * HH];
__device__ float    g_wXf[2 * DD * DD];  // lw^T in mma-B fragment order (tf32)
__device__ float    g_wYf[2 * DD * DD];  // lw^T @ W1ab in fragment order
__device__ float    g_bYv[2 * DD];       // lb @ W1ab
__device__ int      g_cnt[NN];
__device__ int      g_rowptr[NN + 1];
__device__ int      g_bsum[64];
__device__ int4     g_edata[EE];         // {src, type, w_bits, logw_bits}

// ---------------- helpers ---------------------------------------------------
__device__ __forceinline__ float siluf(float x) {
    return __fdividef(x, 1.0f + __expf(-x));
}
__device__ __forceinline__ unsigned f2tf(float x) {
    unsigned r;
    asm("cvt.rna.tf32.f32 %0, %1;" : "=r"(r) : "f"(x));
    return r;
}
__device__ __forceinline__ void mma8(float* c, const unsigned* a,
                                     unsigned b0, unsigned b1) {
    asm volatile(
        "mma.sync.aligned.m16n8k8.row.col.f32.tf32.tf32.f32 "
        "{%0,%1,%2,%3}, {%4,%5,%6,%7}, {%8,%9}, {%0,%1,%2,%3};"
        : "+f"(c[0]), "+f"(c[1]), "+f"(c[2]), "+f"(c[3])
        : "r"(a[0]), "r"(a[1]), "r"(a[2]), "r"(a[3]), "r"(b0), "r"(b1));
}

// ============ zoned setup: weight prep (BOTH layers) + counter zero ==========
// blocks   0..127 : prep  (layer = b>>6)  wXf/wYf fragment-order tf32
// blocks 128..159 : prepb (layer = (b-128)>>4)  bY
// blocks 160..223 : wtb   (layer = (b-160)>>5)
// blocks 224..    : zero g_cnt
__global__ void k_setup(const float* __restrict__ lin_w,
                        const float* __restrict__ lin_b,
                        const float* __restrict__ aw1,
                        const float* __restrict__ ab1,
                        const float* __restrict__ eemb) {
    int b   = blockIdx.x;
    int tid = threadIdx.x;
    if (b < 128) {                       // ---- prep ----
        int l   = b >> 6;
        int idx = (b & 63) * 256 + tid;
        const float* lw = lin_w + l * DD * DD;
        const float* w1 = aw1 + l * 3 * DD * HH;
        int k = idx >> 7, c = idx & 127;
        const float* w1c = (c < 64) ? (w1 + c) : (w1 + 128 * 64 + (c - 64));
        float s = 0.f;
#pragma unroll 8
        for (int j = 0; j < 128; j++)
            s = fmaf(__ldg(&lw[j * 128 + k]), __ldg(&w1c[j * 64]), s);
        int koct = k >> 3, klo = k & 7;
        int nb = c >> 3, g = c & 7;
        int off = (koct * 16 + nb) * 64 + (g * 4 + (klo & 3)) * 2 + (klo >> 2);
        g_wYf[l * DD * DD + off] = __uint_as_float(f2tf(s));
        g_wXf[l * DD * DD + off] =
            __uint_as_float(f2tf(__ldg(&lw[c * 128 + k])));
    } else if (b < 160) {                // ---- prepb ----
        int l    = (b - 128) >> 4;
        int c    = ((b - 128) & 15) * 8 + (tid >> 5);
        int lane = tid & 31;
        const float* w1 = aw1 + l * 3 * DD * HH;
        const float* lb = lin_b + l * DD;
        const float* w1c = (c < 64) ? (w1 + c) : (w1 + 128 * 64 + (c - 64));
        float v = 0.f;
#pragma unroll
        for (int i = 0; i < 4; i++) {
            int j = lane + 32 * i;
            v = fmaf(__ldg(&lb[j]), __ldg(&w1c[j * 64]), v);
        }
#pragma unroll
        for (int o = 16; o; o >>= 1) v += __shfl_xor_sync(0xffffffffu, v, o);
        if (lane == 0) g_bYv[l * DD + c] = v;
    } else if (b < 224) {                // ---- wtb ----
        int l    = (b - 160) >> 5;
        int w    = ((b - 160) & 31) * 8 + (tid >> 5);
        int lane = tid & 31;
        const float* emb = eemb + l * TT * DD;
        const float* w1  = aw1 + l * 3 * DD * HH;
        const float* b1  = ab1 + l * HH;
        int t = w >> 6, h = w & 63;
        float s = 0.f;
#pragma unroll
        for (int i = 0; i < 4; i++) {
            int k = lane + 32 * i;
            s = fmaf(__ldg(&emb[t * DD + k]),
                     __ldg(&w1[(2 * DD + k) * HH + h]), s);
        }
#pragma unroll
        for (int o = 16; o; o >>= 1) s += __shfl_xor_sync(0xffffffffu, s, o);
        if (lane == 0) g_wtb[l * TT * HH + w] = s + __ldg(&b1[h]);
    } else {                             // ---- zero g_cnt ----
        int i = (b - 224) * 256 + tid;
        if (i < NN) g_cnt[i] = 0;
    }
}

// ================== CSR build (graph identical for both layers) ==============
__global__ void k_hist(const int* __restrict__ ei) {
    int e = blockIdx.x * blockDim.x + threadIdx.x;
    if (e < EE) atomicAdd(&g_cnt[__ldg(&ei[EE + e])], 1);
}
__global__ void k_scan1() {
    __shared__ int wsum[32];
    int tid  = threadIdx.x;
    int lane = tid & 31, wid = tid >> 5;
    int i = blockIdx.x * 1024 + tid;
    int v = (i < NN) ? g_cnt[i] : 0;
    int x = v;
#pragma unroll
    for (int o = 1; o < 32; o <<= 1) {
        int y = __shfl_up_sync(0xffffffffu, x, o);
        if (lane >= o) x += y;
    }
    if (lane == 31) wsum[wid] = x;
    __syncthreads();
    if (wid == 0) {
        int y = wsum[lane];
#pragma unroll
        for (int o = 1; o < 32; o <<= 1) {
            int z = __shfl_up_sync(0xffffffffu, y, o);
            if (lane >= o) y += z;
        }
        wsum[lane] = y;
    }
    __syncthreads();
    int wpref = (wid > 0) ? wsum[wid - 1] : 0;
    if (i < NN) g_rowptr[i] = x + wpref - v;
    if (tid == 1023) g_bsum[blockIdx.x] = x + wpref;
}
__global__ void k_scan2(int nblk) {
    __shared__ int w0tot;
    int tid  = threadIdx.x;
    int lane = tid & 31, wid = tid >> 5;
    int v = (tid < nblk) ? g_bsum[tid] : 0;
    int x = v;
#pragma unroll
    for (int o = 1; o < 32; o <<= 1) {
        int y = __shfl_up_sync(0xffffffffu, x, o);
        if (lane >= o) x += y;
    }
    if (tid == 31) w0tot = x;
    __syncthreads();
    if (wid == 1) x += w0tot;
    if (tid < nblk) g_bsum[tid] = x - v;
    if (tid == nblk - 1) g_rowptr[NN] = x;
}
__global__ void k_scan3() {
    int i = blockIdx.x * 1024 + threadIdx.x;
    if (i < NN) { g_rowptr[i] += g_bsum[blockIdx.x]; g_cnt[i] = 0; }
}
__global__ void k_scatter(const int* __restrict__ ei,
                          const int* __restrict__ et,
                          const float* __restrict__ ew) {
    int e = blockIdx.x * blockDim.x + threadIdx.x;
    if (e >= EE) return;
    int dst = __ldg(&ei[EE + e]);
    int pos = g_rowptr[dst] + atomicAdd(&g_cnt[dst], 1);
    float w = __ldg(&ew[e]);
    g_edata[pos] = make_int4(__ldg(&ei[e]), __ldg(&et[e]),
                             __float_as_int(w),
                             __float_as_int(logf(fmaxf(w, 1e-6f))));
}

// -------- unified tf32 GEMM: merged phases — one A load, both weights --------
__global__ __launch_bounds__(256, 2) void k_gemm2(
    const float* __restrict__ xh, const float* __restrict__ curv,
    const float* __restrict__ lb, int layer) {
    extern __shared__ float sm[];
    float* AF = sm;             // [4 m16][16 ksg][AFS]
    const float* wXf = g_wXf + layer * DD * DD;
    const float* wYf = g_wYf + layer * DD * DD;
    const float* bY  = g_bYv + layer * DD;
    int tid  = threadIdx.x;
    int lane = tid & 31;
    int w    = tid >> 5;
    int g    = lane >> 2;
    int t    = lane & 3;
    int mw   = w & 1;
    int nw   = w >> 1;
    int n0   = blockIdx.x * TM;

    // prologue: log-map 8 rows per warp (pairs for ILP), scatter to AF
    {
        float c   = fminf(fmaxf(__ldg(&curv[0]), 0.1f), 10.0f);
        float sqc = sqrtf(c);
        int rbase = w * 8;
        int ksg_w = lane >> 1;
        int khi_w = lane & 1;
#pragma unroll
        for (int rr = 0; rr < 8; rr += 2) {
            int mA = rbase + rr, mB = mA + 1;
            int nA = n0 + mA, nB = n0 + mB;
            float spA[4] = {0.f, 0.f, 0.f, 0.f};
            float spB[4] = {0.f, 0.f, 0.f, 0.f};
            float x0A = 1.f, x0B = 1.f, nsA = 0.f, nsB = 0.f;
            if (nA < NN) {
                const float* row = xh + (size_t)nA * 129;
                x0A = __ldg(&row[0]);
#pragma unroll
                for (int i = 0; i < 4; i++) {
                    spA[i] = __ldg(&row[1 + 4 * lane + i]);
                    nsA += spA[i] * spA[i];
                }
            }
            if (nB < NN) {
                const float* row = xh + (size_t)nB * 129;
                x0B = __ldg(&row[0]);
#pragma unroll
                for (int i = 0; i < 4; i++) {
                    spB[i] = __ldg(&row[1 + 4 * lane + i]);
                    nsB += spB[i] * spB[i];
                }
            }
#pragma unroll
            for (int o = 16; o; o >>= 1) {
                nsA += __shfl_xor_sync(0xffffffffu, nsA, o);
                nsB += __shfl_xor_sync(0xffffffffu, nsB, o);
            }
            float nrmA = fmaxf(sqrtf(nsA), 1e-6f);
            float nrmB = fmaxf(sqrtf(nsB), 1e-6f);
            float scA = (nA < NN)
                ? acoshf(fmaxf(sqc * x0A, 1.0f + 1e-7f)) / (sqc * nrmA) : 0.f;
            float scB = (nB < NN)
                ? acoshf(fmaxf(sqc * x0B, 1.0f + 1e-7f)) / (sqc * nrmB) : 0.f;
            float4 xvA = make_float4(spA[0] * scA, spA[1] * scA,
                                     spA[2] * scA, spA[3] * scA);
            float4 xvB = make_float4(spB[0] * scB, spB[1] * scB,
                                     spB[2] * scB, spB[3] * scB);
            if (nA < NN) *(float4*)&g_xtan[(size_t)nA * DD + 4 * lane] = xvA;
            if (nB < NN) *(float4*)&g_xtan[(size_t)nB * DD + 4 * lane] = xvB;
            {
                int m16 = mA >> 4, gr = mA & 7, hi = (mA >> 3) & 1;
                float* base = &AF[(m16 * 16 + ksg_w) * AFS + hi + 2 * khi_w];
                base[(gr * 4 + 0) * 4] = __uint_as_float(f2tf(xvA.x));
                base[(gr * 4 + 1) * 4] = __uint_as_float(f2tf(xvA.y));
                base[(gr * 4 + 2) * 4] = __uint_as_float(f2tf(xvA.z));
                base[(gr * 4 + 3) * 4] = __uint_as_float(f2tf(xvA.w));
            }
            {
                int m16 = mB >> 4, gr = mB & 7, hi = (mB >> 3) & 1;
                float* base = &AF[(m16 * 16 + ksg_w) * AFS + hi + 2 * khi_w];
                base[(gr * 4 + 0) * 4] = __uint_as_float(f2tf(xvB.x));
                base[(gr * 4 + 1) * 4] = __uint_as_float(f2tf(xvB.y));
                base[(gr * 4 + 2) * 4] = __uint_as_float(f2tf(xvB.z));
                base[(gr * 4 + 3) * 4] = __uint_as_float(f2tf(xvB.w));
            }
        }
    }
    __syncthreads();  // AF complete; no further barriers

    float accX[2][4][4], accY[2][4][4];
#pragma unroll
    for (int mi = 0; mi < 2; mi++)
#pragma unroll
        for (int nj = 0; nj < 4; nj++)
#pragma unroll
            for (int q = 0; q < 4; q++) {
                accX[mi][nj][q] = 0.f;
                accY[mi][nj][q] = 0.f;
            }

#pragma unroll 2
    for (int ksg = 0; ksg < 16; ksg++) {
        float2 bX[4], bY2[4];
#pragma unroll
        for (int nj = 0; nj < 4; nj++) {
            int off = (ksg * 16 + nw * 4 + nj) * 64 + lane * 2;
            bX[nj]  = *(const float2*)&wXf[off];
            bY2[nj] = *(const float2*)&wYf[off];
        }
        unsigned a[2][4];
#pragma unroll
        for (int mi = 0; mi < 2; mi++) {
            float4 af = *(const float4*)
                &AF[((mw * 2 + mi) * 16 + ksg) * AFS + lane * 4];
            a[mi][0] = __float_as_uint(af.x);
            a[mi][1] = __float_as_uint(af.y);
            a[mi][2] = __float_as_uint(af.z);
            a[mi][3] = __float_as_uint(af.w);
        }
#pragma unroll
        for (int nj = 0; nj < 4; nj++) {
            mma8(accX[0][nj], a[0], __float_as_uint(bX[nj].x),
                 __float_as_uint(bX[nj].y));
            mma8(accX[1][nj], a[1], __float_as_uint(bX[nj].x),
                 __float_as_uint(bX[nj].y));
            mma8(accY[0][nj], a[0], __float_as_uint(bY2[nj].x),
                 __float_as_uint(bY2[nj].y));
            mma8(accY[1][nj], a[1], __float_as_uint(bY2[nj].x),
                 __float_as_uint(bY2[nj].y));
        }
    }

    // epilogue: phase-X -> g_xlin (+lb), phase-Y -> u/v (+bY)
#pragma unroll
    for (int mi = 0; mi < 2; mi++)
#pragma unroll
        for (int nj = 0; nj < 4; nj++) {
            int cb = nw * 32 + nj * 8 + 2 * t;
            int rl0 = mw * 32 + mi * 16 + g, rl1 = rl0 + 8;
            int gn0 = n0 + rl0, gn1 = n0 + rl1;
            float lb0 = __ldg(&lb[cb]), lb1 = __ldg(&lb[cb + 1]);
            float by0 = bY[cb],         by1 = bY[cb + 1];
            float2 sx0 = make_float2(accX[mi][nj][0] + lb0,
                                     accX[mi][nj][1] + lb1);
            float2 sx1 = make_float2(accX[mi][nj][2] + lb0,
                                     accX[mi][nj][3] + lb1);
            float2 sy0 = make_float2(accY[mi][nj][0] + by0,
                                     accY[mi][nj][1] + by1);
            float2 sy1 = make_float2(accY[mi][nj][2] + by0,
                                     accY[mi][nj][3] + by1);
            if (gn0 < NN) *(float2*)&g_xlin[(size_t)gn0 * DD + cb] = sx0;
            if (gn1 < NN) *(float2*)&g_xlin[(size_t)gn1 * DD + cb] = sx1;
            if (cb < 64) {
                if (gn0 < NN) *(float2*)&g_u[(size_t)gn0 * HH + cb] = sy0;
                if (gn1 < NN) *(float2*)&g_u[(size_t)gn1 * HH + cb] = sy1;
            } else {
                if (gn0 < NN) *(float2*)&g_v[(size_t)gn0 * HH + cb - 64] = sy0;
                if (gn1 < NN) *(float2*)&g_v[(size_t)gn1 * HH + cb - 64] = sy1;
            }
        }
}

// ====== fused per-dst: no-max softmax (scores tiny) + agg + LN + exp map =====
__global__ __launch_bounds__(256) void k_fused(
    const float* __restrict__ emb,
    const float* __restrict__ aw2, const float* __restrict__ ab2,
    const float* __restrict__ sib, const float* __restrict__ lng,
    const float* __restrict__ lnb, const float* __restrict__ curv,
    float* __restrict__ out, int layer) {
    __shared__ float swtb[TT * HH];
    __shared__ float sw2[HH];
    __shared__ float semb[TT * DD];
    int tid = threadIdx.x;
    if (tid < TT * HH) swtb[tid] = g_wtb[layer * TT * HH + tid];
    if (tid < HH) sw2[tid] = __ldg(&aw2[tid]);
    for (int i = tid; i < TT * DD; i += 256) semb[i] = __ldg(&emb[i]);
    __syncthreads();

    int n    = blockIdx.x * 8 + (tid >> 5);
    int lane = tid & 31;
    if (n >= NN) return;
    float b2 = __ldg(&ab2[0]);
    float sb = __ldg(&sib[0]);
    float2 uu = *(const float2*)&g_u[(size_t)n * HH + 2 * lane];
    float w2a = sw2[2 * lane], w2b = sw2[2 * lane + 1];

    int p0 = g_rowptr[n], p1 = g_rowptr[n + 1];
    float s = 0.f;
    float a0 = 0.f, a1 = 0.f, a2 = 0.f, a3 = 0.f;
    int p = p0;
    for (; p + 2 <= p1; p += 2) {
        int4 e0 = __ldg(&g_edata[p]);
        int4 e1 = __ldg(&g_edata[p + 1]);
        float2 v0 = *(const float2*)&g_v[(size_t)e0.x * HH + 2 * lane];
        float2 v1 = *(const float2*)&g_v[(size_t)e1.x * HH + 2 * lane];
        float4 x0 = *(const float4*)&g_xlin[(size_t)e0.x * DD + 4 * lane];
        float4 x1 = *(const float4*)&g_xlin[(size_t)e1.x * DD + 4 * lane];
        float z0a = uu.x + v0.x + swtb[e0.y * HH + 2 * lane];
        float z0b = uu.y + v0.y + swtb[e0.y * HH + 2 * lane + 1];
        float z1a = uu.x + v1.x + swtb[e1.y * HH + 2 * lane];
        float z1b = uu.y + v1.y + swtb[e1.y * HH + 2 * lane + 1];
        float pp0 = siluf(z0a) * w2a + siluf(z0b) * w2b;
        float pp1 = siluf(z1a) * w2a + siluf(z1b) * w2b;
#pragma unroll
        for (int o = 16; o; o >>= 1) {
            pp0 += __shfl_xor_sync(0xffffffffu, pp0, o);
            pp1 += __shfl_xor_sync(0xffffffffu, pp1, o);
        }
        float s0 = pp0 + b2 + __int_as_float(e0.w);
        float s1 = pp1 + b2 + __int_as_float(e1.w);
        if (e0.y == 1) s0 += sb;
        if (e1.y == 1) s1 += sb;
        float ex0 = __expf(s0);
        float ex1 = __expf(s1);
        s += ex0 + ex1;
        float cw0 = ex0 * __int_as_float(e0.z);
        float cw1 = ex1 * __int_as_float(e1.z);
        const float4 m0 = *(const float4*)&semb[e0.y * DD + 4 * lane];
        const float4 m1 = *(const float4*)&semb[e1.y * DD + 4 * lane];
        a0 += cw0 * (x0.x + m0.x) + cw1 * (x1.x + m1.x);
        a1 += cw0 * (x0.y + m0.y) + cw1 * (x1.y + m1.y);
        a2 += cw0 * (x0.z + m0.z) + cw1 * (x1.z + m1.z);
        a3 += cw0 * (x0.w + m0.w) + cw1 * (x1.w + m1.w);
    }
    if (p < p1) {
        int4 e0 = __ldg(&g_edata[p]);
        float2 v0 = *(const float2*)&g_v[(size_t)e0.x * HH + 2 * lane];
        float4 x0 = *(const float4*)&g_xlin[(size_t)e0.x * DD + 4 * lane];
        float z0a = uu.x + v0.x + swtb[e0.y * HH + 2 * lane];
        float z0b = uu.y + v0.y + swtb[e0.y * HH + 2 * lane + 1];
        float pp0 = siluf(z0a) * w2a + siluf(z0b) * w2b;
#pragma unroll
        for (int o = 16; o; o >>= 1)
            pp0 += __shfl_xor_sync(0xffffffffu, pp0, o);
        float s0 = pp0 + b2 + __int_as_float(e0.w);
        if (e0.y == 1) s0 += sb;
        float ex0 = __expf(s0);
        s += ex0;
        float cw0 = ex0 * __int_as_float(e0.z);
        const float4 m0 = *(const float4*)&semb[e0.y * DD + 4 * lane];
        a0 += cw0 * (x0.x + m0.x);
        a1 += cw0 * (x0.y + m0.y);
        a2 += cw0 * (x0.z + m0.z);
        a3 += cw0 * (x0.w + m0.w);
    }
    float inv = __fdividef(1.f, s + 1e-16f);

    float4 xt = *(const float4*)&g_xtan[(size_t)n * DD + 4 * lane];
    float x[4];
    x[0] = xt.x + a0 * inv; x[1] = xt.y + a1 * inv;
    x[2] = xt.z + a2 * inv; x[3] = xt.w + a3 * inv;
    float smv = x[0] + x[1] + x[2] + x[3];
#pragma unroll
    for (int o = 16; o; o >>= 1) smv += __shfl_xor_sync(0xffffffffu, smv, o);
    float mu = smv * (1.0f / 128.0f);
    float vs = 0.f;
#pragma unroll
    for (int i = 0; i < 4; i++) { float d = x[i] - mu; vs += d * d; }
#pragma unroll
    for (int o = 16; o; o >>= 1) vs += __shfl_xor_sync(0xffffffffu, vs, o);
    float rinv = rsqrtf(vs * (1.0f / 128.0f) + 1e-5f);
    float y[4];
    float n2 = 0.f;
#pragma unroll
    for (int i = 0; i < 4; i++) {
        y[i] = (x[i] - mu) * rinv * __ldg(&lng[4 * lane + i]) +
               __ldg(&lnb[4 * lane + i]);
        n2 += y[i] * y[i];
    }
#pragma unroll
    for (int o = 16; o; o >>= 1) n2 += __shfl_xor_sync(0xffffffffu, n2, o);
    float c   = fminf(fmaxf(__ldg(&curv[0]), 0.1f), 10.0f);
    float sqc = sqrtf(c);
    float nrm = fmaxf(sqrtf(n2), 1e-6f);
    float th  = sqc * nrm;
    float scale = sinhf(th) / (sqc * nrm);
    float* orow = out + (size_t)n * 129;
    if (lane == 0) orow[0] = coshf(th) / sqc;
#pragma unroll
    for (int i = 0; i < 4; i++) orow[1 + 4 * lane + i] = y[i] * scale;
}

// ---------------- host ------------------------------------------------------
extern "C" void kernel_launch(void* const* d_in, const int* in_sizes, int n_in,
                              void* d_out, int out_size) {
    const float* x_hyp = (const float*)d_in[0];
    const int*   ei    = (const int*)d_in[1];
    const int*   et    = (const int*)d_in[2];
    const float* ew    = (const float*)d_in[3];
    const float* lin_w = (const float*)d_in[4];
    const float* lin_b = (const float*)d_in[5];
    const float* ln_g  = (const float*)d_in[6];
    const float* ln_b  = (const float*)d_in[7];
    const float* eemb  = (const float*)d_in[8];
    const float* aw1   = (const float*)d_in[9];
    const float* ab1   = (const float*)d_in[10];
    const float* aw2   = (const float*)d_in[11];
    const float* ab2   = (const float*)d_in[12];
    const float* sib   = (const float*)d_in[13];
    const float* curv  = (const float*)d_in[14];
    float* out = (float*)d_out;
    (void)in_sizes; (void)n_in; (void)out_size;

    cudaFuncSetAttribute(k_gemm2, cudaFuncAttributeMaxDynamicSharedMemorySize,
                         GEMM_SMEM);

    const int NSCAN = (NN + 1023) / 1024;      // 49
    const int NZB   = (NN + 255) / 256;        // 196 (zero-blocks)
    // zoned setup: 128 prep + 32 prepb + 64 wtb + NZB zero blocks
    k_setup<<<224 + NZB, 256>>>(lin_w, lin_b, aw1, ab1, eemb);
    k_hist<<<(EE + 255) / 256, 256>>>(ei);
    k_scan1<<<NSCAN, 1024>>>();
    // k_gemm2 L0 at launch index 3 (ncu profiles index 3)
    k_gemm2<<<(NN + TM - 1) / TM, 256, GEMM_SMEM>>>(x_hyp, curv + 0, lin_b, 0);
    k_scan2<<<1, 64>>>(NSCAN);
    k_scan3<<<NSCAN, 1024>>>();
    k_scatter<<<(EE + 255) / 256, 256>>>(ei, et, ew);
    k_fused<<<(NN + 7) / 8, 256>>>(eemb, aw2, ab2, sib, ln_g, ln_b, curv,
                                   out, 0);
    // layer 1
    k_gemm2<<<(NN + TM - 1) / TM, 256, GEMM_SMEM>>>(out, curv + 1,
                                                    lin_b + DD, 1);
    k_fused<<<(NN + 7) / 8, 256>>>(eemb + TT * DD, aw2 + HH, ab2 + 1, sib + 1,
                                   ln_g + DD, ln_b + DD, curv + 1, out, 1);
}